// round 15
// baseline (speedup 1.0000x reference)
#include <cuda_runtime.h>
#include <math.h>
#include <stdint.h>

#define H 128
#define MAXE 480000
#define MAXN 20000

// ---- scratch (no allocations allowed) ----
__device__ float g_denom[MAXN];
__device__ float g_p[MAXN];
__device__ float g_P[(size_t)MAXN * H];      // hV @ W1v + b1 (fp32)
__device__ float g_dh[(size_t)MAXN * H];
// frag-packed tf32 edge weights, LANE-CONTIGUOUS:
// [layer(3)][ntile(16)][kpair(8)][lane(32)][q(4)]
__device__ __align__(256) float g_wr[3 * 16384];
// pre-rounded (tf32) node FFN weights, original layout
__device__ __align__(256) float g_wi[128 * 512];
__device__ __align__(256) float g_wo[512 * 128];

// ---------------------------------------------------------------------------
__device__ __forceinline__ float to_tf32(float x) {
    uint32_t u;
    asm("cvt.rna.tf32.f32 %0, %1;" : "=r"(u) : "f"(x));
    return __uint_as_float(u);
}
__device__ __forceinline__ void mma_tf32(float d[4], const uint32_t a[4],
                                         uint32_t b0, uint32_t b1) {
    asm volatile(
        "mma.sync.aligned.m16n8k8.row.col.f32.tf32.tf32.f32 "
        "{%0,%1,%2,%3}, {%4,%5,%6,%7}, {%8,%9}, {%0,%1,%2,%3};"
        : "+f"(d[0]), "+f"(d[1]), "+f"(d[2]), "+f"(d[3])
        : "r"(a[0]), "r"(a[1]), "r"(a[2]), "r"(a[3]), "r"(b0), "r"(b1));
}
#define CP_ASYNC16(dst32, srcp) \
    asm volatile("cp.async.cg.shared.global [%0], [%1], 16;" :: "r"(dst32), "l"(srcp))
#define CP_COMMIT() asm volatile("cp.async.commit_group;" ::: "memory")
#define CP_WAIT1()  asm volatile("cp.async.wait_group 1;" ::: "memory")
#define CP_WAIT0()  asm volatile("cp.async.wait_group 0;" ::: "memory")

// frag-packed A offset (128x128 tf32 in smem)
__device__ __forceinline__ int a_off(int r, int k) {
    int blk  = ((r >> 4) << 4) + (k >> 3);
    int slot = ((((r & 7) << 2) | (k & 3)) ^ ((k >> 3) & 7));
    int frag = ((r >> 3) & 1) | (((k >> 2) & 1) << 1);
    return (blk << 7) + (slot << 2) + frag;
}

// ---------------------------------------------------------------------------
// prew: pack edge weights + pre-round node FFN weights
// ---------------------------------------------------------------------------
__global__ void prew_kernel(const float* __restrict__ w1,
                            const float* __restrict__ w2,
                            const float* __restrict__ w3,
                            const float* __restrict__ wi,
                            const float* __restrict__ wo) {
    int i = blockIdx.x * blockDim.x + threadIdx.x;
    if (i < 3 * 16384) {
        int q    = i & 3;
        int lane = (i >> 2) & 31;
        int p    = (i >> 7) & 7;
        int jg   = (i >> 10) & 15;
        int l    = i >> 14;
        int ks = 2 * p + (q >> 1);
        int b  = q & 1;
        int k = ks * 8 + (lane & 3) + 4 * b;
        int n = jg * 8 + (lane >> 2);
        const float* src = (l == 0) ? (w1 + (size_t)(128 + k) * 128 + n)
                         : (l == 1) ? (w2 + (size_t)k * 128 + n)
                                    : (w3 + (size_t)k * 128 + n);
        g_wr[i] = to_tf32(*src);
    } else if (i < 3 * 16384 + 65536) {
        int j = i - 3 * 16384;
        g_wi[j] = to_tf32(wi[j]);
    } else if (i < 3 * 16384 + 131072) {
        int j = i - 3 * 16384 - 65536;
        g_wo[j] = to_tf32(wo[j]);
    }
}

// ---------------------------------------------------------------------------
// 64-k warp GEMM chunk (32x32 warp tile) — p_kernel
// ---------------------------------------------------------------------------
__device__ __forceinline__ void wg_tf32(const float* sA, int lda, int aoff,
                                        const float* sW, float acc[2][4][4],
                                        int m0, int n0, int lx, int ly) {
#pragma unroll
    for (int kk = 0; kk < 8; kk++) {
        int kb = kk * 8;
        uint32_t a[2][4];
#pragma unroll
        for (int i = 0; i < 2; i++) {
            const float* ap = sA + (m0 + 16 * i + ly) * lda + aoff + kb + lx;
            a[i][0] = __float_as_uint(ap[0]);
            a[i][1] = __float_as_uint(ap[8 * lda]);
            a[i][2] = __float_as_uint(ap[4]);
            a[i][3] = __float_as_uint(ap[8 * lda + 4]);
        }
#pragma unroll
        for (int j = 0; j < 4; j++) {
            const float* bp = sW + (kb + lx) * 136 + n0 + 8 * j + ly;
            uint32_t b0 = __float_as_uint(bp[0]);
            uint32_t b1 = __float_as_uint(bp[4 * 136]);
#pragma unroll
            for (int i = 0; i < 2; i++) mma_tf32(acc[i][j], a[i], b0, b1);
        }
    }
}

// 32-k warp GEMM half-chunk (32x32 warp tile) — node pipeline
__device__ __forceinline__ void wg32_tf32(const float* sA, int koff,
                                          const float* sW, float acc[2][4][4],
                                          int m0, int n0, int lx, int ly) {
#pragma unroll
    for (int kk = 0; kk < 4; kk++) {
        int kb = kk * 8;
        uint32_t a[2][4];
#pragma unroll
        for (int i = 0; i < 2; i++) {
            const float* ap = sA + (m0 + 16 * i + ly) * 132 + koff + kb + lx;
            a[i][0] = __float_as_uint(ap[0]);
            a[i][1] = __float_as_uint(ap[8 * 132]);
            a[i][2] = __float_as_uint(ap[4]);
            a[i][3] = __float_as_uint(ap[8 * 132 + 4]);
        }
#pragma unroll
        for (int j = 0; j < 4; j++) {
            const float* bp = sW + (kb + lx) * 136 + n0 + 8 * j + ly;
            uint32_t b0 = __float_as_uint(bp[0]);
            uint32_t b1 = __float_as_uint(bp[4 * 136]);
#pragma unroll
            for (int i = 0; i < 2; i++) mma_tf32(acc[i][j], a[i], b0, b1);
        }
    }
}

// ---------------------------------------------------------------------------
// p_kernel: P[n] = hV[n] @ w1[0:128] + b1 ; g_p[n] = hV[n] . A[0:128]
// ALSO zeroes g_dh rows + g_denom for its nodes.
// ---------------------------------------------------------------------------
constexpr int P_SMEM = (64 * 132 + 64 * 136) * 4;

__global__ void __launch_bounds__(256, 2)
p_kernel(const float* __restrict__ hV, const float* __restrict__ w1,
         const float* __restrict__ b1, const float* __restrict__ A, int N)
{
    extern __shared__ float smf[];
    float* s_a = smf;
    float* s_w = smf + 64 * 132;

    const int t = threadIdx.x;
    const int nb0 = blockIdx.x * 64;
    const int w = t >> 5, lane = t & 31;
    const int lx = lane & 3, ly = lane >> 2;
    const int m0 = (w & 1) * 32, n0 = (w >> 1) * 32;

#pragma unroll
    for (int jj = 0; jj < 8; jj++) {
        int idx = t + 256 * jj;
        int r = idx >> 5, c4 = idx & 31;
        int n = nb0 + r;
        if (n < N)
            *reinterpret_cast<float4*>(g_dh + (size_t)n * H + c4 * 4) =
                make_float4(0.f, 0.f, 0.f, 0.f);
    }
    if (t < 64 && nb0 + t < N) g_denom[nb0 + t] = 0.f;

#pragma unroll
    for (int jj = 0; jj < 8; jj++) {
        int idx = t + 256 * jj;
        int r = idx >> 5, c4 = idx & 31;
        int n = nb0 + r;
        float4 v = make_float4(0.f, 0.f, 0.f, 0.f);
        if (n < N) v = *reinterpret_cast<const float4*>(hV + (size_t)n * H + c4 * 4);
        v.x = to_tf32(v.x); v.y = to_tf32(v.y); v.z = to_tf32(v.z); v.w = to_tf32(v.w);
        *reinterpret_cast<float4*>(s_a + r * 132 + c4 * 4) = v;
    }

    // fused att_node
    {
        int r = t >> 2, p3 = t & 3;
        int n = nb0 + r;
        if (n < N) {
            float s = 0.f;
#pragma unroll
            for (int q = 0; q < 8; q++) {
                float4 v = *reinterpret_cast<const float4*>(hV + (size_t)n * H + p3 * 32 + q * 4);
                float4 a = *reinterpret_cast<const float4*>(A + p3 * 32 + q * 4);
                s += v.x * a.x + v.y * a.y + v.z * a.z + v.w * a.w;
            }
            s += __shfl_xor_sync(0xffffffffu, s, 1);
            s += __shfl_xor_sync(0xffffffffu, s, 2);
            if (p3 == 0) g_p[n] = s;
        }
    }

    float acc[2][4][4];
#pragma unroll
    for (int i = 0; i < 2; i++)
#pragma unroll
        for (int j = 0; j < 4; j++)
#pragma unroll
            for (int q = 0; q < 4; q++) acc[i][j][q] = 0.f;

    for (int kc = 0; kc < 2; kc++) {
        __syncthreads();
#pragma unroll
        for (int jj = 0; jj < 8; jj++) {
            int idx = t + 256 * jj;
            int k = idx >> 5, c4 = idx & 31;
            float4 v = *reinterpret_cast<const float4*>(
                w1 + (size_t)(kc * 64 + k) * 128 + c4 * 4);
            v.x = to_tf32(v.x); v.y = to_tf32(v.y); v.z = to_tf32(v.z); v.w = to_tf32(v.w);
            *reinterpret_cast<float4*>(s_w + k * 136 + c4 * 4) = v;
        }
        __syncthreads();
        wg_tf32(s_a, 132, kc * 64, s_w, acc, m0, n0, lx, ly);
    }
#pragma unroll
    for (int j = 0; j < 4; j++) {
        int col = n0 + 8 * j + 2 * lx;
        float bb0 = __ldg(b1 + col), bb1 = __ldg(b1 + col + 1);
#pragma unroll
        for (int i = 0; i < 2; i++) {
#pragma unroll
            for (int hf = 0; hf < 2; hf++) {
                int r = m0 + 16 * i + ly + 8 * hf;
                int n = nb0 + r;
                if (n < N) {
                    float2 v = make_float2(acc[i][j][2 * hf] + bb0,
                                           acc[i][j][2 * hf + 1] + bb1);
                    *reinterpret_cast<float2*>(g_P + (size_t)n * H + col) = v;
                }
            }
        }
    }
}

// ---------------------------------------------------------------------------
// edge kernel (round-11/14 configuration, verbatim)
// ---------------------------------------------------------------------------
constexpr int S_BW   = 16384;
constexpr int S_COEF = S_BW + 8192;
constexpr int S_DST  = S_COEF + 128;
constexpr int EDGE_SMEM = (S_DST + 128) * 4;   // 99328

__global__ void __launch_bounds__(256, 2)
edge_mma_kernel(const float* __restrict__ hE, const int* __restrict__ eidx,
                const float* __restrict__ A,
                const float* __restrict__ b2, const float* __restrict__ b3, int E)
{
    extern __shared__ float sm[];
    float* s_ha   = sm;
    float* s_coef = sm + S_COEF;
    int*   s_dst  = (int*)(sm + S_DST);
    const uint32_t sb = (uint32_t)__cvta_generic_to_shared(sm);

    const int t = threadIdx.x;
    const int e0 = blockIdx.x * 128;
    const int w = t >> 5, lane = t & 31;
    const int lx = lane & 3, ly = lane >> 2;
    const int m0 = (w & 3) * 32, n0 = (w >> 2) * 64;
    const int tmw = (w & 3) * 2;
    const int jbase = (w >> 2) * 8;

    if (t < 128) {
        int e = e0 + t;
        s_dst[t] = (e < E) ? eidx[e] : 0;
    }

#pragma unroll
    for (int c = 0; c < 2; c++) {
        const float* src = g_wr + ((c & 3) << 8);
        uint32_t dstb = sb + (S_BW + c * 4096) * 4;
#pragma unroll
        for (int it = 0; it < 4; it++) {
            int f = t + 256 * it;
            int nt = f >> 6, wi2 = f & 63;
            CP_ASYNC16(dstb + (nt * 256 + wi2 * 4) * 4, src + nt * 1024 + wi2 * 4);
        }
        CP_COMMIT();
    }

#pragma unroll
    for (int jj = 0; jj < 16; jj++) {
        int c4 = (t & 7) | ((jj & 3) << 3);
        int r  = ((t >> 3) & 31) | ((jj >> 2) << 5);
        float4 v = make_float4(0.f, 0.f, 0.f, 0.f);
        if (e0 + r < E)
            v = *reinterpret_cast<const float4*>(hE + (size_t)(e0 + r) * H + c4 * 4);
        int k0 = c4 * 4;
        s_ha[a_off(r, k0    )] = to_tf32(v.x);
        s_ha[a_off(r, k0 + 1)] = to_tf32(v.y);
        s_ha[a_off(r, k0 + 2)] = to_tf32(v.z);
        s_ha[a_off(r, k0 + 3)] = to_tf32(v.w);
    }
    __syncthreads();

    {
        int r = t >> 1, ph = t & 1;
        int e = e0 + r;
        if (e < E) {
            float s = 0.f;
            const float* he = hE + (size_t)e * H + ph * 64;
            const float* av = A + 128 + ph * 64;
#pragma unroll
            for (int q = 0; q < 16; q++) {
                float4 v = *reinterpret_cast<const float4*>(he + q * 4);
                float4 a = *reinterpret_cast<const float4*>(av + q * 4);
                s += v.x * a.x + v.y * a.y + v.z * a.z + v.w * a.w;
            }
            s += __shfl_xor_sync(0xffffffffu, s, 1);
            if (ph == 0) {
                int d = s_dst[r];
                s += g_p[d];
                float lr = (s >= 0.f) ? s : 0.01f * s;
                float sg = 1.f / (1.f + expf(-lr));
                float att = expf(sg);
                s_coef[r] = att;
                atomicAdd(&g_denom[d], att);
            }
        } else if (ph == 0) {
            s_coef[r] = 0.f;
        }
    }

    float acc[2][8][4];
#pragma unroll
    for (int i = 0; i < 2; i++)
#pragma unroll
        for (int j = 0; j < 8; j++)
#pragma unroll
            for (int q = 0; q < 4; q++) acc[i][j][q] = 0.f;

    for (int c = 0; c < 12; c++) {
        if (c < 11) CP_WAIT1(); else CP_WAIT0();
        __syncthreads();

        {
            const float* bwp = sm + S_BW + (c & 1) * 4096 + (jbase << 8) + (lane << 2);
#pragma unroll
            for (int half = 0; half < 2; half++) {
                uint32_t a[2][2][4];
#pragma unroll
                for (int kh = 0; kh < 2; kh++) {
                    int ksg = ((c & 3) << 2) + half * 2 + kh;
#pragma unroll
                    for (int i = 0; i < 2; i++) {
                        float4 av = *reinterpret_cast<const float4*>(
                            s_ha + ((((tmw + i) << 4) + ksg) << 7)
                                 + ((lane ^ (ksg & 7)) << 2));
                        a[kh][i][0] = __float_as_uint(av.x);
                        a[kh][i][1] = __float_as_uint(av.y);
                        a[kh][i][2] = __float_as_uint(av.z);
                        a[kh][i][3] = __float_as_uint(av.w);
                    }
                }
#pragma unroll
                for (int jb = 0; jb < 2; jb++) {
                    float4 bq[4];
#pragma unroll
                    for (int j = 0; j < 4; j++)
                        bq[j] = *reinterpret_cast<const float4*>(
                            bwp + (((jb * 4 + j) << 8) + (half << 7)));
#pragma unroll
                    for (int kh = 0; kh < 2; kh++)
#pragma unroll
                        for (int j = 0; j < 4; j++) {
                            uint32_t b0 = __float_as_uint(kh ? bq[j].z : bq[j].x);
                            uint32_t b1 = __float_as_uint(kh ? bq[j].w : bq[j].y);
                            mma_tf32(acc[0][jb * 4 + j], a[kh][0], b0, b1);
                            mma_tf32(acc[1][jb * 4 + j], a[kh][1], b0, b1);
                        }
                }
            }
        }

        if (c == 3) {
            __syncthreads();
#pragma unroll
            for (int j = 0; j < 8; j++) {
                int col = n0 + 8 * j + 2 * lx;
#pragma unroll
                for (int i2 = 0; i2 < 2; i2++) {
#pragma unroll
                    for (int hf = 0; hf < 2; hf++) {
                        int r = m0 + 16 * i2 + ly + 8 * hf;
                        float2 p2 = *reinterpret_cast<const float2*>(
                            g_P + (size_t)s_dst[r] * H + col);
                        float v0 = acc[i2][j][2 * hf]     + p2.x;
                        float v1 = acc[i2][j][2 * hf + 1] + p2.y;
                        v0 = (v0 >= 0.f) ? v0 : 0.01f * v0;
                        v1 = (v1 >= 0.f) ? v1 : 0.01f * v1;
                        s_ha[a_off(r, col)]     = to_tf32(v0);
                        s_ha[a_off(r, col + 1)] = to_tf32(v1);
                        acc[i2][j][2 * hf] = 0.f; acc[i2][j][2 * hf + 1] = 0.f;
                    }
                }
            }
            __syncthreads();
        } else if (c == 7) {
            __syncthreads();
#pragma unroll
            for (int j = 0; j < 8; j++) {
                int col = n0 + 8 * j + 2 * lx;
                float bb0 = __ldg(b2 + col), bb1 = __ldg(b2 + col + 1);
#pragma unroll
                for (int i2 = 0; i2 < 2; i2++) {
#pragma unroll
                    for (int hf = 0; hf < 2; hf++) {
                        int r = m0 + 16 * i2 + ly + 8 * hf;
                        float v0 = acc[i2][j][2 * hf]     + bb0;
                        float v1 = acc[i2][j][2 * hf + 1] + bb1;
                        v0 = (v0 >= 0.f) ? v0 : 0.01f * v0;
                        v1 = (v1 >= 0.f) ? v1 : 0.01f * v1;
                        s_ha[a_off(r, col)]     = to_tf32(v0);
                        s_ha[a_off(r, col + 1)] = to_tf32(v1);
                        acc[i2][j][2 * hf] = 0.f; acc[i2][j][2 * hf + 1] = 0.f;
                    }
                }
            }
            __syncthreads();
        } else if (c < 10) {
            __syncthreads();
        }

        if (c < 10) {
            int cn = c + 2;
            const float* src = g_wr + ((cn >> 2) << 14) + ((cn & 3) << 8);
            uint32_t dstb = sb + (S_BW + (cn & 1) * 4096) * 4;
#pragma unroll
            for (int it = 0; it < 4; it++) {
                int f = t + 256 * it;
                int nt = f >> 6, wi2 = f & 63;
                CP_ASYNC16(dstb + (nt * 256 + wi2 * 4) * 4, src + nt * 1024 + wi2 * 4);
            }
            CP_COMMIT();
        }
    }

#pragma unroll
    for (int j = 0; j < 8; j++) {
        int col = n0 + 8 * j + 2 * lx;
        float bb0 = __ldg(b3 + col), bb1 = __ldg(b3 + col + 1);
#pragma unroll
        for (int i2 = 0; i2 < 2; i2++) {
#pragma unroll
            for (int hf = 0; hf < 2; hf++) {
                int r = m0 + 16 * i2 + ly + 8 * hf;
                if (e0 + r < E) {
                    float cf = s_coef[r];
                    float2 v = make_float2((acc[i2][j][2 * hf]     + bb0) * cf,
                                           (acc[i2][j][2 * hf + 1] + bb1) * cf);
                    atomicAdd(reinterpret_cast<float2*>(
                                  &g_dh[(size_t)s_dst[r] * H + col]), v);
                }
            }
        }
    }
}

// ---------------------------------------------------------------------------
// node tf32 MMA kernel: cp.async double-buffered weight pipeline.
// 32 half-chunks (32 k-rows): chunk c -> ch=c>>3, phase=(c>>2)&1 (0=wi,1=wo),
// sub=c&3. Epilogue (relu -> s_hm) after c%8==3. Math order identical.
// smem floats: s_x 64x132 | s_hm 64x132 | s_w 2 x 32x136  (same size as before)
// ---------------------------------------------------------------------------
constexpr int NS_W = 2 * 64 * 132;
constexpr int NODE_SMEM = (NS_W + 2 * 32 * 136) * 4;

template <bool ROUND>
__device__ __forceinline__ void ln64(float* s, const float* __restrict__ gain,
                                     const float* __restrict__ bias) {
    int t = threadIdx.x;
    int r = t >> 2, p = t & 3;
    float* row = s + r * 132;
    float sm = 0.f, sq = 0.f;
#pragma unroll
    for (int c = p; c < 128; c += 4) {
        float v = row[c];
        sm += v; sq += v * v;
    }
    sm += __shfl_xor_sync(0xffffffffu, sm, 1);
    sq += __shfl_xor_sync(0xffffffffu, sq, 1);
    sm += __shfl_xor_sync(0xffffffffu, sm, 2);
    sq += __shfl_xor_sync(0xffffffffu, sq, 2);
    float mu  = sm * (1.f / 128.f);
    float var = sq * (1.f / 128.f) - mu * mu;
    float rs  = rsqrtf(var + 1e-6f);
#pragma unroll
    for (int c = p; c < 128; c += 4) {
        float v = gain[c] * (row[c] - mu) * rs + bias[c];
        row[c] = ROUND ? to_tf32(v) : v;
    }
}

// stage one 32x128 weight half-chunk via cp.async (1024 float4 / 256 thr)
__device__ __forceinline__ void node_stage(uint32_t sb, int c) {
    const int t = threadIdx.x;
    int ch = c >> 3, phase = (c >> 2) & 1, sub = c & 3;
    uint32_t dstb = sb + (NS_W + (c & 1) * 32 * 136) * 4;
#pragma unroll
    for (int it = 0; it < 4; it++) {
        int f = t + 256 * it;
        int row = f >> 5, c4 = f & 31;
        const float* src = (phase == 0)
            ? g_wi + (size_t)(sub * 32 + row) * 512 + ch * 128 + c4 * 4
            : g_wo + (size_t)(ch * 128 + sub * 32 + row) * 128 + c4 * 4;
        CP_ASYNC16(dstb + (row * 136 + c4 * 4) * 4, src);
    }
    CP_COMMIT();
}

__global__ void __launch_bounds__(256, 2)
node_mma_kernel(const float* __restrict__ hV,
                const float* __restrict__ bi, const float* __restrict__ bo,
                const float* __restrict__ g1, const float* __restrict__ be1,
                const float* __restrict__ g2, const float* __restrict__ be2,
                float* __restrict__ out, int N)
{
    extern __shared__ float smf[];
    float* s_x  = smf;
    float* s_hm = smf + 64 * 132;
    const uint32_t sb = (uint32_t)__cvta_generic_to_shared(smf);

    const int t = threadIdx.x;
    const int nb0 = blockIdx.x * 64;
    const int w = t >> 5, lane = t & 31;
    const int lx = lane & 3, ly = lane >> 2;
    const int m0 = (w & 1) * 32, n0 = (w >> 1) * 32;

    node_stage(sb, 0);
    node_stage(sb, 1);

#pragma unroll
    for (int jj = 0; jj < 8; jj++) {
        int idx = t + 256 * jj;
        int r = idx >> 5, c4 = idx & 31;
        int n = nb0 + r;
        float4 x = make_float4(0.f, 0.f, 0.f, 0.f);
        if (n < N) {
            float den = g_denom[n];
            float cf = (den > 0.f) ? 1.f / (den * 30.f) : 0.f;
            float4 h = *reinterpret_cast<const float4*>(hV + (size_t)n * H + c4 * 4);
            float4 d = *reinterpret_cast<const float4*>(g_dh + (size_t)n * H + c4 * 4);
            x = make_float4(h.x + d.x * cf, h.y + d.y * cf,
                            h.z + d.z * cf, h.w + d.w * cf);
        }
        *reinterpret_cast<float4*>(s_x + r * 132 + c4 * 4) = x;
    }
    __syncthreads();
    ln64<true>(s_x, g1, be1);
    __syncthreads();

    float tacc[2][4][4], oacc[2][4][4];
#pragma unroll
    for (int i = 0; i < 2; i++)
#pragma unroll
        for (int j = 0; j < 4; j++)
#pragma unroll
            for (int q = 0; q < 4; q++) { tacc[i][j][q] = 0.f; oacc[i][j][q] = 0.f; }

    for (int c = 0; c < 32; c++) {
        if (c < 31) CP_WAIT1(); else CP_WAIT0();
        __syncthreads();

        {
            int phase = (c >> 2) & 1, sub = c & 3;
            const float* bw = smf + NS_W + (c & 1) * 32 * 136;
            const float* sA = phase ? s_hm : s_x;
            wg32_tf32(sA, sub * 32, bw, phase ? oacc : tacc, m0, n0, lx, ly);
        }

        if ((c & 7) == 3) {
            int ch = c >> 3;
            __syncthreads();
            // relu epilogue: s_hm = tf32(relu(tacc + bi[ch])); reset tacc
#pragma unroll
            for (int j = 0; j < 4; j++) {
                int col = n0 + 8 * j + 2 * lx;
                float bb0 = __ldg(bi + ch * 128 + col);
                float bb1 = __ldg(bi + ch * 128 + col + 1);
#pragma unroll
                for (int i = 0; i < 2; i++) {
                    int r = m0 + 16 * i + ly;
                    s_hm[r * 132 + col]           = to_tf32(fmaxf(tacc[i][j][0] + bb0, 0.f));
                    s_hm[r * 132 + col + 1]       = to_tf32(fmaxf(tacc[i][j][1] + bb1, 0.f));
                    s_hm[(r + 8) * 132 + col]     = to_tf32(fmaxf(tacc[i][j][2] + bb0, 0.f));
                    s_hm[(r + 8) * 132 + col + 1] = to_tf32(fmaxf(tacc[i][j][3] + bb1, 0.f));
#pragma unroll
                    for (int q = 0; q < 4; q++) tacc[i][j][q] = 0.f;
                }
            }
            __syncthreads();
        } else if (c < 30) {
            __syncthreads();
        }

        if (c < 30) node_stage(sb, c + 2);
    }

    // z = x + ffn + bo -> s_hm ; LN2 ; store
    __syncthreads();
#pragma unroll
    for (int j = 0; j < 4; j++) {
        int col = n0 + 8 * j + 2 * lx;
        float bb0 = __ldg(bo + col), bb1 = __ldg(bo + col + 1);
#pragma unroll
        for (int i = 0; i < 2; i++) {
            int r = m0 + 16 * i + ly;
            s_hm[r * 132 + col]           = s_x[r * 132 + col] + oacc[i][j][0] + bb0;
            s_hm[r * 132 + col + 1]       = s_x[r * 132 + col + 1] + oacc[i][j][1] + bb1;
            s_hm[(r + 8) * 132 + col]     = s_x[(r + 8) * 132 + col] + oacc[i][j][2] + bb0;
            s_hm[(r + 8) * 132 + col + 1] = s_x[(r + 8) * 132 + col + 1] + oacc[i][j][3] + bb1;
        }
    }
    __syncthreads();
    ln64<false>(s_hm, g2, be2);
    __syncthreads();

#pragma unroll
    for (int jj = 0; jj < 8; jj++) {
        int idx = t + 256 * jj;
        int r = idx >> 5, c4 = idx & 31;
        int n = nb0 + r;
        if (n < N)
            *reinterpret_cast<float4*>(out + (size_t)n * H + c4 * 4) =
                *reinterpret_cast<const float4*>(s_hm + r * 132 + c4 * 4);
    }
}

// ---------------------------------------------------------------------------
extern "C" void kernel_launch(void* const* d_in, const int* in_sizes, int n_in,
                              void* d_out, int out_size)
{
    const float* hV  = (const float*)d_in[0];
    const float* hE  = (const float*)d_in[1];
    const float* w1  = (const float*)d_in[2];
    const float* b1  = (const float*)d_in[3];
    const float* w2  = (const float*)d_in[4];
    const float* b2  = (const float*)d_in[5];
    const float* w3  = (const float*)d_in[6];
    const float* b3  = (const float*)d_in[7];
    const float* A   = (const float*)d_in[8];
    const float* wi  = (const float*)d_in[9];
    const float* bi  = (const float*)d_in[10];
    const float* wo  = (const float*)d_in[11];
    const float* bo  = (const float*)d_in[12];
    const float* g1  = (const float*)d_in[13];
    const float* be1 = (const float*)d_in[14];
    const float* g2  = (const float*)d_in[15];
    const float* be2 = (const float*)d_in[16];
    const int*   eix = (const int*)d_in[17];

    int N = in_sizes[0] / H;
    int E = in_sizes[17] / 2;
    float* out = (float*)d_out;

    cudaFuncSetAttribute(edge_mma_kernel, cudaFuncAttributeMaxDynamicSharedMemorySize, EDGE_SMEM);
    cudaFuncSetAttribute(node_mma_kernel, cudaFuncAttributeMaxDynamicSharedMemorySize, NODE_SMEM);
    cudaFuncSetAttribute(p_kernel, cudaFuncAttributeMaxDynamicSharedMemorySize, P_SMEM);

    prew_kernel<<<(3 * 16384 + 131072 + 255) / 256, 256>>>(w1, w2, w3, wi, wo);
    p_kernel<<<(N + 63) / 64, 256, P_SMEM>>>(hV, w1, b1, A, N);
    edge_mma_kernel<<<(E + 127) / 128, 256, EDGE_SMEM>>>(hE, eix, A, b2, b3, E);
    node_mma_kernel<<<(N + 63) / 64, 256, NODE_SMEM>>>(hV, bi, bo,
                                                       g1, be1, g2, be2, out, N);
}

// round 16
// speedup vs baseline: 1.0887x; 1.0887x over previous
#include <cuda_runtime.h>
#include <math.h>
#include <stdint.h>

#define H 128
#define MAXE 480000
#define MAXN 20000

// ---- scratch (no allocations allowed) ----
__device__ float g_denom[MAXN];
__device__ float g_p[MAXN];
__device__ float g_P[(size_t)MAXN * H];      // hV @ W1v + b1 (fp32)
__device__ float g_dh[(size_t)MAXN * H];
// frag-packed tf32 edge weights, LANE-CONTIGUOUS:
// [layer(3)][ntile(16)][kpair(8)][lane(32)][q(4)]
__device__ __align__(256) float g_wr[3 * 16384];
// stream-packed tf32 node FFN weights in consume order:
// stage s (0..15): ch=s>>2, phase=(s>>1)&1 (0=wi,1=wo), k0=(s&1)*64
// g_wn[s*8192 + k*128 + col]
__device__ __align__(256) float g_wn[16 * 8192];

// ---------------------------------------------------------------------------
__device__ __forceinline__ float to_tf32(float x) {
    uint32_t u;
    asm("cvt.rna.tf32.f32 %0, %1;" : "=r"(u) : "f"(x));
    return __uint_as_float(u);
}
__device__ __forceinline__ void mma_tf32(float d[4], const uint32_t a[4],
                                         uint32_t b0, uint32_t b1) {
    asm volatile(
        "mma.sync.aligned.m16n8k8.row.col.f32.tf32.tf32.f32 "
        "{%0,%1,%2,%3}, {%4,%5,%6,%7}, {%8,%9}, {%0,%1,%2,%3};"
        : "+f"(d[0]), "+f"(d[1]), "+f"(d[2]), "+f"(d[3])
        : "r"(a[0]), "r"(a[1]), "r"(a[2]), "r"(a[3]), "r"(b0), "r"(b1));
}
#define CP_ASYNC16(dst32, srcp) \
    asm volatile("cp.async.cg.shared.global [%0], [%1], 16;" :: "r"(dst32), "l"(srcp))
#define CP_COMMIT() asm volatile("cp.async.commit_group;" ::: "memory")
#define CP_WAIT1()  asm volatile("cp.async.wait_group 1;" ::: "memory")
#define CP_WAIT0()  asm volatile("cp.async.wait_group 0;" ::: "memory")

// frag-packed A offset (128x128 tf32 in smem)
__device__ __forceinline__ int a_off(int r, int k) {
    int blk  = ((r >> 4) << 4) + (k >> 3);
    int slot = ((((r & 7) << 2) | (k & 3)) ^ ((k >> 3) & 7));
    int frag = ((r >> 3) & 1) | (((k >> 2) & 1) << 1);
    return (blk << 7) + (slot << 2) + frag;
}

// ---------------------------------------------------------------------------
// prew: pack edge weights (frag order) + node FFN weights (stream order)
// total elems: 3*16384 + 131072 = 180224
// ---------------------------------------------------------------------------
__global__ void prew_kernel(const float* __restrict__ w1,
                            const float* __restrict__ w2,
                            const float* __restrict__ w3,
                            const float* __restrict__ wi,
                            const float* __restrict__ wo) {
    int i = blockIdx.x * blockDim.x + threadIdx.x;
    if (i < 3 * 16384) {
        int q    = i & 3;
        int lane = (i >> 2) & 31;
        int p    = (i >> 7) & 7;
        int jg   = (i >> 10) & 15;
        int l    = i >> 14;
        int ks = 2 * p + (q >> 1);
        int b  = q & 1;
        int k = ks * 8 + (lane & 3) + 4 * b;
        int n = jg * 8 + (lane >> 2);
        const float* src = (l == 0) ? (w1 + (size_t)(128 + k) * 128 + n)
                         : (l == 1) ? (w2 + (size_t)k * 128 + n)
                                    : (w3 + (size_t)k * 128 + n);
        g_wr[i] = to_tf32(*src);
    } else if (i < 3 * 16384 + 131072) {
        int j = i - 3 * 16384;
        int col = j & 127;
        int k   = (j >> 7) & 63;
        int s   = j >> 13;
        int ch = s >> 2, phase = (s >> 1) & 1, k0 = (s & 1) * 64;
        const float* src = (phase == 0)
            ? wi + (size_t)(k0 + k) * 512 + ch * 128 + col
            : wo + (size_t)(ch * 128 + k0 + k) * 128 + col;
        g_wn[j] = to_tf32(*src);
    }
}

// ---------------------------------------------------------------------------
// 64-k warp GEMM chunk (32x32 warp tile)
// ---------------------------------------------------------------------------
__device__ __forceinline__ void wg_tf32(const float* sA, int lda, int aoff,
                                        const float* sW, float acc[2][4][4],
                                        int m0, int n0, int lx, int ly) {
#pragma unroll
    for (int kk = 0; kk < 8; kk++) {
        int kb = kk * 8;
        uint32_t a[2][4];
#pragma unroll
        for (int i = 0; i < 2; i++) {
            const float* ap = sA + (m0 + 16 * i + ly) * lda + aoff + kb + lx;
            a[i][0] = __float_as_uint(ap[0]);
            a[i][1] = __float_as_uint(ap[8 * lda]);
            a[i][2] = __float_as_uint(ap[4]);
            a[i][3] = __float_as_uint(ap[8 * lda + 4]);
        }
#pragma unroll
        for (int j = 0; j < 4; j++) {
            const float* bp = sW + (kb + lx) * 136 + n0 + 8 * j + ly;
            uint32_t b0 = __float_as_uint(bp[0]);
            uint32_t b1 = __float_as_uint(bp[4 * 136]);
#pragma unroll
            for (int i = 0; i < 2; i++) mma_tf32(acc[i][j], a[i], b0, b1);
        }
    }
}

// ---------------------------------------------------------------------------
// p_kernel: P[n] = hV[n] @ w1[0:128] + b1 ; g_p[n] = hV[n] . A[0:128]
// ALSO zeroes g_dh rows + g_denom for its nodes.
// ---------------------------------------------------------------------------
constexpr int P_SMEM = (64 * 132 + 64 * 136) * 4;

__global__ void __launch_bounds__(256, 2)
p_kernel(const float* __restrict__ hV, const float* __restrict__ w1,
         const float* __restrict__ b1, const float* __restrict__ A, int N)
{
    extern __shared__ float smf[];
    float* s_a = smf;
    float* s_w = smf + 64 * 132;

    const int t = threadIdx.x;
    const int nb0 = blockIdx.x * 64;
    const int w = t >> 5, lane = t & 31;
    const int lx = lane & 3, ly = lane >> 2;
    const int m0 = (w & 1) * 32, n0 = (w >> 1) * 32;

#pragma unroll
    for (int jj = 0; jj < 8; jj++) {
        int idx = t + 256 * jj;
        int r = idx >> 5, c4 = idx & 31;
        int n = nb0 + r;
        if (n < N)
            *reinterpret_cast<float4*>(g_dh + (size_t)n * H + c4 * 4) =
                make_float4(0.f, 0.f, 0.f, 0.f);
    }
    if (t < 64 && nb0 + t < N) g_denom[nb0 + t] = 0.f;

#pragma unroll
    for (int jj = 0; jj < 8; jj++) {
        int idx = t + 256 * jj;
        int r = idx >> 5, c4 = idx & 31;
        int n = nb0 + r;
        float4 v = make_float4(0.f, 0.f, 0.f, 0.f);
        if (n < N) v = *reinterpret_cast<const float4*>(hV + (size_t)n * H + c4 * 4);
        v.x = to_tf32(v.x); v.y = to_tf32(v.y); v.z = to_tf32(v.z); v.w = to_tf32(v.w);
        *reinterpret_cast<float4*>(s_a + r * 132 + c4 * 4) = v;
    }

    // fused att_node
    {
        int r = t >> 2, p3 = t & 3;
        int n = nb0 + r;
        if (n < N) {
            float s = 0.f;
#pragma unroll
            for (int q = 0; q < 8; q++) {
                float4 v = *reinterpret_cast<const float4*>(hV + (size_t)n * H + p3 * 32 + q * 4);
                float4 a = *reinterpret_cast<const float4*>(A + p3 * 32 + q * 4);
                s += v.x * a.x + v.y * a.y + v.z * a.z + v.w * a.w;
            }
            s += __shfl_xor_sync(0xffffffffu, s, 1);
            s += __shfl_xor_sync(0xffffffffu, s, 2);
            if (p3 == 0) g_p[n] = s;
        }
    }

    float acc[2][4][4];
#pragma unroll
    for (int i = 0; i < 2; i++)
#pragma unroll
        for (int j = 0; j < 4; j++)
#pragma unroll
            for (int q = 0; q < 4; q++) acc[i][j][q] = 0.f;

    for (int kc = 0; kc < 2; kc++) {
        __syncthreads();
#pragma unroll
        for (int jj = 0; jj < 8; jj++) {
            int idx = t + 256 * jj;
            int k = idx >> 5, c4 = idx & 31;
            float4 v = *reinterpret_cast<const float4*>(
                w1 + (size_t)(kc * 64 + k) * 128 + c4 * 4);
            v.x = to_tf32(v.x); v.y = to_tf32(v.y); v.z = to_tf32(v.z); v.w = to_tf32(v.w);
            *reinterpret_cast<float4*>(s_w + k * 136 + c4 * 4) = v;
        }
        __syncthreads();
        wg_tf32(s_a, 132, kc * 64, s_w, acc, m0, n0, lx, ly);
    }
#pragma unroll
    for (int j = 0; j < 4; j++) {
        int col = n0 + 8 * j + 2 * lx;
        float bb0 = __ldg(b1 + col), bb1 = __ldg(b1 + col + 1);
#pragma unroll
        for (int i = 0; i < 2; i++) {
#pragma unroll
            for (int hf = 0; hf < 2; hf++) {
                int r = m0 + 16 * i + ly + 8 * hf;
                int n = nb0 + r;
                if (n < N) {
                    float2 v = make_float2(acc[i][j][2 * hf] + bb0,
                                           acc[i][j][2 * hf + 1] + bb1);
                    *reinterpret_cast<float2*>(g_P + (size_t)n * H + col) = v;
                }
            }
        }
    }
}

// ---------------------------------------------------------------------------
// edge kernel (round-11/14 configuration, verbatim)
// ---------------------------------------------------------------------------
constexpr int S_BW   = 16384;
constexpr int S_COEF = S_BW + 8192;
constexpr int S_DST  = S_COEF + 128;
constexpr int EDGE_SMEM = (S_DST + 128) * 4;   // 99328

__global__ void __launch_bounds__(256, 2)
edge_mma_kernel(const float* __restrict__ hE, const int* __restrict__ eidx,
                const float* __restrict__ A,
                const float* __restrict__ b2, const float* __restrict__ b3, int E)
{
    extern __shared__ float sm[];
    float* s_ha   = sm;
    float* s_coef = sm + S_COEF;
    int*   s_dst  = (int*)(sm + S_DST);
    const uint32_t sb = (uint32_t)__cvta_generic_to_shared(sm);

    const int t = threadIdx.x;
    const int e0 = blockIdx.x * 128;
    const int w = t >> 5, lane = t & 31;
    const int lx = lane & 3, ly = lane >> 2;
    const int m0 = (w & 3) * 32, n0 = (w >> 2) * 64;
    const int tmw = (w & 3) * 2;
    const int jbase = (w >> 2) * 8;

    if (t < 128) {
        int e = e0 + t;
        s_dst[t] = (e < E) ? eidx[e] : 0;
    }

#pragma unroll
    for (int c = 0; c < 2; c++) {
        const float* src = g_wr + ((c & 3) << 8);
        uint32_t dstb = sb + (S_BW + c * 4096) * 4;
#pragma unroll
        for (int it = 0; it < 4; it++) {
            int f = t + 256 * it;
            int nt = f >> 6, wi2 = f & 63;
            CP_ASYNC16(dstb + (nt * 256 + wi2 * 4) * 4, src + nt * 1024 + wi2 * 4);
        }
        CP_COMMIT();
    }

#pragma unroll
    for (int jj = 0; jj < 16; jj++) {
        int c4 = (t & 7) | ((jj & 3) << 3);
        int r  = ((t >> 3) & 31) | ((jj >> 2) << 5);
        float4 v = make_float4(0.f, 0.f, 0.f, 0.f);
        if (e0 + r < E)
            v = *reinterpret_cast<const float4*>(hE + (size_t)(e0 + r) * H + c4 * 4);
        int k0 = c4 * 4;
        s_ha[a_off(r, k0    )] = to_tf32(v.x);
        s_ha[a_off(r, k0 + 1)] = to_tf32(v.y);
        s_ha[a_off(r, k0 + 2)] = to_tf32(v.z);
        s_ha[a_off(r, k0 + 3)] = to_tf32(v.w);
    }
    __syncthreads();

    {
        int r = t >> 1, ph = t & 1;
        int e = e0 + r;
        if (e < E) {
            float s = 0.f;
            const float* he = hE + (size_t)e * H + ph * 64;
            const float* av = A + 128 + ph * 64;
#pragma unroll
            for (int q = 0; q < 16; q++) {
                float4 v = *reinterpret_cast<const float4*>(he + q * 4);
                float4 a = *reinterpret_cast<const float4*>(av + q * 4);
                s += v.x * a.x + v.y * a.y + v.z * a.z + v.w * a.w;
            }
            s += __shfl_xor_sync(0xffffffffu, s, 1);
            if (ph == 0) {
                int d = s_dst[r];
                s += g_p[d];
                float lr = (s >= 0.f) ? s : 0.01f * s;
                float sg = 1.f / (1.f + expf(-lr));
                float att = expf(sg);
                s_coef[r] = att;
                atomicAdd(&g_denom[d], att);
            }
        } else if (ph == 0) {
            s_coef[r] = 0.f;
        }
    }

    float acc[2][8][4];
#pragma unroll
    for (int i = 0; i < 2; i++)
#pragma unroll
        for (int j = 0; j < 8; j++)
#pragma unroll
            for (int q = 0; q < 4; q++) acc[i][j][q] = 0.f;

    for (int c = 0; c < 12; c++) {
        if (c < 11) CP_WAIT1(); else CP_WAIT0();
        __syncthreads();

        {
            const float* bwp = sm + S_BW + (c & 1) * 4096 + (jbase << 8) + (lane << 2);
#pragma unroll
            for (int half = 0; half < 2; half++) {
                uint32_t a[2][2][4];
#pragma unroll
                for (int kh = 0; kh < 2; kh++) {
                    int ksg = ((c & 3) << 2) + half * 2 + kh;
#pragma unroll
                    for (int i = 0; i < 2; i++) {
                        float4 av = *reinterpret_cast<const float4*>(
                            s_ha + ((((tmw + i) << 4) + ksg) << 7)
                                 + ((lane ^ (ksg & 7)) << 2));
                        a[kh][i][0] = __float_as_uint(av.x);
                        a[kh][i][1] = __float_as_uint(av.y);
                        a[kh][i][2] = __float_as_uint(av.z);
                        a[kh][i][3] = __float_as_uint(av.w);
                    }
                }
#pragma unroll
                for (int jb = 0; jb < 2; jb++) {
                    float4 bq[4];
#pragma unroll
                    for (int j = 0; j < 4; j++)
                        bq[j] = *reinterpret_cast<const float4*>(
                            bwp + (((jb * 4 + j) << 8) + (half << 7)));
#pragma unroll
                    for (int kh = 0; kh < 2; kh++)
#pragma unroll
                        for (int j = 0; j < 4; j++) {
                            uint32_t b0 = __float_as_uint(kh ? bq[j].z : bq[j].x);
                            uint32_t b1 = __float_as_uint(kh ? bq[j].w : bq[j].y);
                            mma_tf32(acc[0][jb * 4 + j], a[kh][0], b0, b1);
                            mma_tf32(acc[1][jb * 4 + j], a[kh][1], b0, b1);
                        }
                }
            }
        }

        if (c == 3) {
            __syncthreads();
#pragma unroll
            for (int j = 0; j < 8; j++) {
                int col = n0 + 8 * j + 2 * lx;
#pragma unroll
                for (int i2 = 0; i2 < 2; i2++) {
#pragma unroll
                    for (int hf = 0; hf < 2; hf++) {
                        int r = m0 + 16 * i2 + ly + 8 * hf;
                        float2 p2 = *reinterpret_cast<const float2*>(
                            g_P + (size_t)s_dst[r] * H + col);
                        float v0 = acc[i2][j][2 * hf]     + p2.x;
                        float v1 = acc[i2][j][2 * hf + 1] + p2.y;
                        v0 = (v0 >= 0.f) ? v0 : 0.01f * v0;
                        v1 = (v1 >= 0.f) ? v1 : 0.01f * v1;
                        s_ha[a_off(r, col)]     = to_tf32(v0);
                        s_ha[a_off(r, col + 1)] = to_tf32(v1);
                        acc[i2][j][2 * hf] = 0.f; acc[i2][j][2 * hf + 1] = 0.f;
                    }
                }
            }
            __syncthreads();
        } else if (c == 7) {
            __syncthreads();
#pragma unroll
            for (int j = 0; j < 8; j++) {
                int col = n0 + 8 * j + 2 * lx;
                float bb0 = __ldg(b2 + col), bb1 = __ldg(b2 + col + 1);
#pragma unroll
                for (int i2 = 0; i2 < 2; i2++) {
#pragma unroll
                    for (int hf = 0; hf < 2; hf++) {
                        int r = m0 + 16 * i2 + ly + 8 * hf;
                        float v0 = acc[i2][j][2 * hf]     + bb0;
                        float v1 = acc[i2][j][2 * hf + 1] + bb1;
                        v0 = (v0 >= 0.f) ? v0 : 0.01f * v0;
                        v1 = (v1 >= 0.f) ? v1 : 0.01f * v1;
                        s_ha[a_off(r, col)]     = to_tf32(v0);
                        s_ha[a_off(r, col + 1)] = to_tf32(v1);
                        acc[i2][j][2 * hf] = 0.f; acc[i2][j][2 * hf + 1] = 0.f;
                    }
                }
            }
            __syncthreads();
        } else if (c < 10) {
            __syncthreads();
        }

        if (c < 10) {
            int cn = c + 2;
            const float* src = g_wr + ((cn >> 2) << 14) + ((cn & 3) << 8);
            uint32_t dstb = sb + (S_BW + (cn & 1) * 4096) * 4;
#pragma unroll
            for (int it = 0; it < 4; it++) {
                int f = t + 256 * it;
                int nt = f >> 6, wi2 = f & 63;
                CP_ASYNC16(dstb + (nt * 256 + wi2 * 4) * 4, src + nt * 1024 + wi2 * 4);
            }
            CP_COMMIT();
        }
    }

#pragma unroll
    for (int j = 0; j < 8; j++) {
        int col = n0 + 8 * j + 2 * lx;
        float bb0 = __ldg(b3 + col), bb1 = __ldg(b3 + col + 1);
#pragma unroll
        for (int i2 = 0; i2 < 2; i2++) {
#pragma unroll
            for (int hf = 0; hf < 2; hf++) {
                int r = m0 + 16 * i2 + ly + 8 * hf;
                if (e0 + r < E) {
                    float cf = s_coef[r];
                    float2 v = make_float2((acc[i2][j][2 * hf]     + bb0) * cf,
                                           (acc[i2][j][2 * hf + 1] + bb1) * cf);
                    atomicAdd(reinterpret_cast<float2*>(
                                  &g_dh[(size_t)s_dst[r] * H + col]), v);
                }
            }
        }
    }
}

// ---------------------------------------------------------------------------
// node tf32 MMA kernel: round-14 structure (16 coarse stages, single buffer),
// staging = linear cp.async from stream-packed g_wn.
// smem fp32: s_x 64x132 | s_hm 64x132 | s_w 64x136
// ---------------------------------------------------------------------------
constexpr int NS_W = 2 * 64 * 132;
constexpr int NODE_SMEM = (NS_W + 64 * 136) * 4;

template <bool ROUND>
__device__ __forceinline__ void ln64(float* s, const float* __restrict__ gain,
                                     const float* __restrict__ bias) {
    int t = threadIdx.x;
    int r = t >> 2, p = t & 3;
    float* row = s + r * 132;
    float sm = 0.f, sq = 0.f;
#pragma unroll
    for (int c = p; c < 128; c += 4) {
        float v = row[c];
        sm += v; sq += v * v;
    }
    sm += __shfl_xor_sync(0xffffffffu, sm, 1);
    sq += __shfl_xor_sync(0xffffffffu, sq, 1);
    sm += __shfl_xor_sync(0xffffffffu, sm, 2);
    sq += __shfl_xor_sync(0xffffffffu, sq, 2);
    float mu  = sm * (1.f / 128.f);
    float var = sq * (1.f / 128.f) - mu * mu;
    float rs  = rsqrtf(var + 1e-6f);
#pragma unroll
    for (int c = p; c < 128; c += 4) {
        float v = gain[c] * (row[c] - mu) * rs + bias[c];
        row[c] = ROUND ? to_tf32(v) : v;
    }
}

// stage 64x128 weight chunk s from g_wn via linear cp.async
__device__ __forceinline__ void node_stage(uint32_t sb, int s) {
    const int t = threadIdx.x;
    const float* src = g_wn + ((size_t)s << 13);
#pragma unroll
    for (int it = 0; it < 8; it++) {
        int f = t + 256 * it;              // float4 idx 0..2047
        int k = f >> 5, c4 = f & 31;
        CP_ASYNC16(sb + (NS_W + k * 136 + c4 * 4) * 4, src + f * 4);
    }
    CP_COMMIT();
}

__global__ void __launch_bounds__(256, 2)
node_mma_kernel(const float* __restrict__ hV,
                const float* __restrict__ bi, const float* __restrict__ bo,
                const float* __restrict__ g1, const float* __restrict__ be1,
                const float* __restrict__ g2, const float* __restrict__ be2,
                float* __restrict__ out, int N)
{
    extern __shared__ float smf[];
    float* s_x  = smf;
    float* s_hm = smf + 64 * 132;
    float* s_w  = smf + NS_W;
    const uint32_t sb = (uint32_t)__cvta_generic_to_shared(smf);

    const int t = threadIdx.x;
    const int nb0 = blockIdx.x * 64;
    const int w = t >> 5, lane = t & 31;
    const int lx = lane & 3, ly = lane >> 2;
    const int m0 = (w & 1) * 32, n0 = (w >> 1) * 32;

    node_stage(sb, 0);    // prefetch first chunk behind x-load/LN

#pragma unroll
    for (int jj = 0; jj < 8; jj++) {
        int idx = t + 256 * jj;
        int r = idx >> 5, c4 = idx & 31;
        int n = nb0 + r;
        float4 x = make_float4(0.f, 0.f, 0.f, 0.f);
        if (n < N) {
            float den = g_denom[n];
            float cf = (den > 0.f) ? 1.f / (den * 30.f) : 0.f;
            float4 h = *reinterpret_cast<const float4*>(hV + (size_t)n * H + c4 * 4);
            float4 d = *reinterpret_cast<const float4*>(g_dh + (size_t)n * H + c4 * 4);
            x = make_float4(h.x + d.x * cf, h.y + d.y * cf,
                            h.z + d.z * cf, h.w + d.w * cf);
        }
        *reinterpret_cast<float4*>(s_x + r * 132 + c4 * 4) = x;
    }
    __syncthreads();
    ln64<true>(s_x, g1, be1);

    float oacc[2][4][4];
#pragma unroll
    for (int i = 0; i < 2; i++)
#pragma unroll
        for (int j = 0; j < 4; j++)
#pragma unroll
            for (int q = 0; q < 4; q++) oacc[i][j][q] = 0.f;

    for (int ch = 0; ch < 4; ch++) {
        float tacc[2][4][4];
#pragma unroll
        for (int i = 0; i < 2; i++)
#pragma unroll
            for (int j = 0; j < 4; j++)
#pragma unroll
                for (int q = 0; q < 4; q++) tacc[i][j][q] = 0.f;
        for (int k0 = 0; k0 < 128; k0 += 64) {
            int s = ch * 4 + (k0 >> 6);
            if (!(ch == 0 && k0 == 0)) {
                __syncthreads();               // s_w free
                node_stage(sb, s);
            }
            CP_WAIT0();
            __syncthreads();
            wg_tf32(s_x, 132, k0, s_w, tacc, m0, n0, lx, ly);
        }
#pragma unroll
        for (int j = 0; j < 4; j++) {
            int col = n0 + 8 * j + 2 * lx;
            float bb0 = __ldg(bi + ch * 128 + col), bb1 = __ldg(bi + ch * 128 + col + 1);
#pragma unroll
            for (int i = 0; i < 2; i++) {
                int r = m0 + 16 * i + ly;
                s_hm[r * 132 + col]           = to_tf32(fmaxf(tacc[i][j][0] + bb0, 0.f));
                s_hm[r * 132 + col + 1]       = to_tf32(fmaxf(tacc[i][j][1] + bb1, 0.f));
                s_hm[(r + 8) * 132 + col]     = to_tf32(fmaxf(tacc[i][j][2] + bb0, 0.f));
                s_hm[(r + 8) * 132 + col + 1] = to_tf32(fmaxf(tacc[i][j][3] + bb1, 0.f));
            }
        }
        for (int k0 = 0; k0 < 128; k0 += 64) {
            int s = ch * 4 + 2 + (k0 >> 6);
            __syncthreads();
            node_stage(sb, s);
            CP_WAIT0();
            __syncthreads();
            wg_tf32(s_hm, 132, k0, s_w, oacc, m0, n0, lx, ly);
        }
    }
    __syncthreads();
#pragma unroll
    for (int j = 0; j < 4; j++) {
        int col = n0 + 8 * j + 2 * lx;
        float bb0 = __ldg(bo + col), bb1 = __ldg(bo + col + 1);
#pragma unroll
        for (int i = 0; i < 2; i++) {
            int r = m0 + 16 * i + ly;
            s_hm[r * 132 + col]           = s_x[r * 132 + col] + oacc[i][j][0] + bb0;
            s_hm[r * 132 + col + 1]       = s_x[r * 132 + col + 1] + oacc[i][j][1] + bb1;
            s_hm[(r + 8) * 132 + col]     = s_x[(r + 8) * 132 + col] + oacc[i][j][2] + bb0;
            s_hm[(r + 8) * 132 + col + 1] = s_x[(r + 8) * 132 + col + 1] + oacc[i][j][3] + bb1;
        }
    }
    __syncthreads();
    ln64<false>(s_hm, g2, be2);
    __syncthreads();

#pragma unroll
    for (int jj = 0; jj < 8; jj++) {
        int idx = t + 256 * jj;
        int r = idx >> 5, c4 = idx & 31;
        int n = nb0 + r;
        if (n < N)
            *reinterpret_cast<float4*>(out + (size_t)n * H + c4 * 4) =
                *reinterpret_cast<const float4*>(s_hm + r * 132 + c4 * 4);
    }
}

// ---------------------------------------------------------------------------
extern "C" void kernel_launch(void* const* d_in, const int* in_sizes, int n_in,
                              void* d_out, int out_size)
{
    const float* hV  = (const float*)d_in[0];
    const float* hE  = (const float*)d_in[1];
    const float* w1  = (const float*)d_in[2];
    const float* b1  = (const float*)d_in[3];
    const float* w2  = (const float*)d_in[4];
    const float* b2  = (const float*)d_in[5];
    const float* w3  = (const float*)d_in[6];
    const float* b3  = (const float*)d_in[7];
    const float* A   = (const float*)d_in[8];
    const float* wi  = (const float*)d_in[9];
    const float* bi  = (const float*)d_in[10];
    const float* wo  = (const float*)d_in[11];
    const float* bo  = (const float*)d_in[12];
    const float* g1  = (const float*)d_in[13];
    const float* be1 = (const float*)d_in[14];
    const float* g2  = (const float*)d_in[15];
    const float* be2 = (const float*)d_in[16];
    const int*   eix = (const int*)d_in[17];

    int N = in_sizes[0] / H;
    int E = in_sizes[17] / 2;
    float* out = (float*)d_out;

    cudaFuncSetAttribute(edge_mma_kernel, cudaFuncAttributeMaxDynamicSharedMemorySize, EDGE_SMEM);
    cudaFuncSetAttribute(node_mma_kernel, cudaFuncAttributeMaxDynamicSharedMemorySize, NODE_SMEM);
    cudaFuncSetAttribute(p_kernel, cudaFuncAttributeMaxDynamicSharedMemorySize, P_SMEM);

    prew_kernel<<<(3 * 16384 + 131072 + 255) / 256, 256>>>(w1, w2, w3, wi, wo);
    p_kernel<<<(N + 63) / 64, 256, P_SMEM>>>(hV, w1, b1, A, N);
    edge_mma_kernel<<<(E + 127) / 128, 256, EDGE_SMEM>>>(hE, eix, A, b2, b3, E);
    node_mma_kernel<<<(N + 63) / 64, 256, NODE_SMEM>>>(hV, bi, bo,
                                                       g1, be1, g2, be2, out, N);
}